// round 3
// baseline (speedup 1.0000x reference)
#include <cuda_runtime.h>
#include <math.h>

#define B_TOT   4096
#define NWIN    64
#define NTOK    49
#define DIM     192
#define NHEAD   6
#define HDIM    32
#define M_ROWS  (B_TOT * NTOK)     /* 200704 */
#define QKV_N   576

// Scratch (no cudaMalloc allowed). Referenced directly from kernels so that
// kernel_launch needs NO runtime API calls besides launches (capture-safe).
__device__ float g_qkv[(size_t)M_ROWS * QKV_N];   // 462 MB
__device__ float g_ctx[(size_t)M_ROWS * DIM];     // 154 MB

// ---------------------------------------------------------------------------
// Tiled fp32 GEMM:  C[M,N] = A[M,K] @ W^T + bias   (W is [N,K] row-major)
// BM=64, BN=64, BK=16, 256 threads, 4x4 micro-tile per thread.
// ---------------------------------------------------------------------------
__device__ __forceinline__
void gemm_body(const float* __restrict__ A,
               const float* __restrict__ W,
               const float* __restrict__ bias,
               float* __restrict__ C,
               int M, int N, int K)
{
    __shared__ float As[64][16];
    __shared__ float Bs[16][64 + 4];

    const int tid = threadIdx.x;
    const int tx  = tid & 15;
    const int ty  = tid >> 4;
    const int r0  = blockIdx.y * 64;
    const int c0  = blockIdx.x * 64;

    float acc[4][4];
#pragma unroll
    for (int i = 0; i < 4; i++)
#pragma unroll
        for (int j = 0; j < 4; j++) acc[i][j] = 0.f;

    const int a_row = tid >> 2;
    const int a_col = (tid & 3) * 4;
    const int w_j   = tid & 63;
    const int w_kk  = (tid >> 6) * 4;

    for (int k0 = 0; k0 < K; k0 += 16) {
        const float4 av = *reinterpret_cast<const float4*>(
            &A[(size_t)(r0 + a_row) * K + k0 + a_col]);
        As[a_row][a_col + 0] = av.x;
        As[a_row][a_col + 1] = av.y;
        As[a_row][a_col + 2] = av.z;
        As[a_row][a_col + 3] = av.w;
        const float4 wv = *reinterpret_cast<const float4*>(
            &W[(size_t)(c0 + w_j) * K + k0 + w_kk]);
        Bs[w_kk + 0][w_j] = wv.x;
        Bs[w_kk + 1][w_j] = wv.y;
        Bs[w_kk + 2][w_j] = wv.z;
        Bs[w_kk + 3][w_j] = wv.w;
        __syncthreads();

#pragma unroll
        for (int kk = 0; kk < 16; kk++) {
            float a_reg[4], b_reg[4];
#pragma unroll
            for (int i = 0; i < 4; i++) a_reg[i] = As[ty * 4 + i][kk];
#pragma unroll
            for (int j = 0; j < 4; j++) b_reg[j] = Bs[kk][tx * 4 + j];
#pragma unroll
            for (int i = 0; i < 4; i++)
#pragma unroll
                for (int j = 0; j < 4; j++)
                    acc[i][j] += a_reg[i] * b_reg[j];
        }
        __syncthreads();
    }

#pragma unroll
    for (int i = 0; i < 4; i++) {
        const size_t row = (size_t)(r0 + ty * 4 + i);
#pragma unroll
        for (int j = 0; j < 4; j++) {
            const int col = c0 + tx * 4 + j;
            C[row * N + col] = acc[i][j] + bias[col];
        }
    }
}

// QKV GEMM: x[M,192] @ qkv_w^T[192,576] + b  -> g_qkv
__global__ __launch_bounds__(256)
void qkv_gemm_kernel(const float* __restrict__ x,
                     const float* __restrict__ qkv_w,
                     const float* __restrict__ qkv_b)
{
    gemm_body(x, qkv_w, qkv_b, g_qkv, M_ROWS, QKV_N, DIM);
}

// Projection GEMM: g_ctx[M,192] @ proj_w^T[192,192] + b -> out
__global__ __launch_bounds__(256)
void proj_gemm_kernel(const float* __restrict__ proj_w,
                      const float* __restrict__ proj_b,
                      float* __restrict__ out)
{
    gemm_body(g_ctx, proj_w, proj_b, out, M_ROWS, DIM, DIM);
}

// ---------------------------------------------------------------------------
// Fused attention: one block per (window b, head h).
// ---------------------------------------------------------------------------
__global__ __launch_bounds__(256)
void attn_kernel(const float* __restrict__ mask,
                 const float* __restrict__ rpb_table,
                 const int*   __restrict__ rel_idx,
                 float* __restrict__ attn_out,
                 int write_attn)
{
    const int bh = blockIdx.x;
    const int b  = bh / NHEAD;
    const int h  = bh % NHEAD;
    const int tid = threadIdx.x;
    const int mb = b % NWIN;

    __shared__ float qs[NTOK * HDIM];
    __shared__ float ks[NTOK * HDIM];
    __shared__ float vs[NTOK * HDIM];
    __shared__ float s[NTOK * 56];

    const size_t row0 = (size_t)b * NTOK;
    const int qoff = h * HDIM;

    for (int e = tid; e < NTOK * HDIM; e += 256) {
        const int i = e >> 5, d = e & 31;
        const size_t base = (row0 + i) * QKV_N + qoff + d;
        qs[e] = g_qkv[base];
        ks[e] = g_qkv[base + DIM];
        vs[e] = g_qkv[base + 2 * DIM];
    }
    __syncthreads();

    const float scale = 0.1767766952966369f;  // 1/sqrt(32)
    for (int e = tid; e < NTOK * NTOK; e += 256) {
        const int i = e / NTOK, j = e % NTOK;
        float dot = 0.f;
#pragma unroll
        for (int d = 0; d < HDIM; d++)
            dot += qs[i * HDIM + d] * ks[j * HDIM + d];
        const float bias = rpb_table[rel_idx[e] * NHEAD + h];
        const float m    = mask[(size_t)mb * NTOK * NTOK + e];
        s[i * 56 + j] = dot * scale + bias + m;
    }
    __syncthreads();

    // softmax: one thread per row
    if (tid < NTOK) {
        float* rowp = &s[tid * 56];
        float mx = rowp[0];
#pragma unroll
        for (int j = 1; j < NTOK; j++) mx = fmaxf(mx, rowp[j]);
        float sum = 0.f;
#pragma unroll
        for (int j = 0; j < NTOK; j++) {
            const float ev = __expf(rowp[j] - mx);
            rowp[j] = ev;
            sum += ev;
        }
        const float inv = 1.f / sum;
#pragma unroll
        for (int j = 0; j < NTOK; j++) rowp[j] *= inv;
    }
    __syncthreads();

    if (write_attn) {
        float* ao = &attn_out[(size_t)bh * NTOK * NTOK];
        for (int e = tid; e < NTOK * NTOK; e += 256)
            ao[e] = s[(e / NTOK) * 56 + (e % NTOK)];
    }

    for (int e = tid; e < NTOK * HDIM; e += 256) {
        const int i = e >> 5, d = e & 31;
        float acc = 0.f;
#pragma unroll
        for (int j = 0; j < NTOK; j++)
            acc += s[i * 56 + j] * vs[j * HDIM + d];
        g_ctx[(row0 + i) * DIM + qoff + d] = acc;
    }
}

extern "C" void kernel_launch(void* const* d_in, const int* in_sizes, int n_in,
                              void* d_out, int out_size)
{
    const float* x      = (const float*)d_in[0];
    const float* mask   = (const float*)d_in[1];
    const float* qkv_w  = (const float*)d_in[2];
    const float* qkv_b  = (const float*)d_in[3];
    const float* proj_w = (const float*)d_in[4];
    const float* proj_b = (const float*)d_in[5];
    const float* rpb    = (const float*)d_in[6];
    const int*   relidx = (const int*)d_in[7];
    float* out = (float*)d_out;

    const long out_elems  = (long)M_ROWS * DIM;                 // 38,535,168
    const long attn_elems = (long)B_TOT * NHEAD * NTOK * NTOK;  // 59,006,976
    const int write_attn = ((long)out_size >= out_elems + attn_elems) ? 1 : 0;
    float* attn_out = out + out_elems;

    // 1) QKV GEMM
    qkv_gemm_kernel<<<dim3(QKV_N / 64, M_ROWS / 64), 256>>>(x, qkv_w, qkv_b);

    // 2) fused window attention per (b, h)
    attn_kernel<<<B_TOT * NHEAD, 256>>>(mask, rpb, relidx, attn_out, write_attn);

    // 3) projection
    proj_gemm_kernel<<<dim3(DIM / 64, M_ROWS / 64), 256>>>(proj_w, proj_b, out);
}

// round 5
// speedup vs baseline: 2.3522x; 2.3522x over previous
#include <cuda_runtime.h>
#include <math.h>

#define B_TOT   4096
#define NWIN    64
#define NTOK    49
#define DIM     192
#define NHEAD   6
#define HDIM    32
#define M_ROWS  (B_TOT * NTOK)     /* 200704 */
#define QKV_N   576
#define NN      (NTOK * NTOK)      /* 2401 */

// Scratch (no cudaMalloc allowed); referenced directly from kernels.
__device__ float g_qkv[(size_t)M_ROWS * QKV_N];          // 462 MB
__device__ float g_ctx[(size_t)M_ROWS * DIM];            // 154 MB
__device__ float g_bm[(size_t)NWIN * NHEAD * NN];        // 3.7 MB bias+mask

// ---------------------------------------------------------------------------
// Precompute bm[(mb*NHEAD+h)][e] = rpb[rel_idx[e]*NHEAD+h] + mask[mb][e]
// ---------------------------------------------------------------------------
__global__ __launch_bounds__(256)
void bm_kernel(const float* __restrict__ mask,
               const float* __restrict__ rpb_table,
               const int*   __restrict__ rel_idx)
{
    const int mb = blockIdx.x / NHEAD;
    const int h  = blockIdx.x % NHEAD;
    float* dst = &g_bm[(size_t)blockIdx.x * NN];
    const float* msk = &mask[(size_t)mb * NN];
    for (int e = threadIdx.x; e < NN; e += 256)
        dst[e] = rpb_table[rel_idx[e] * NHEAD + h] + msk[e];
}

// ---------------------------------------------------------------------------
// fp32 GEMM: C[M,N] = A[M,K] @ W^T + bias, W row-major [N,K]
// BM=128, BN=64, BK=16, 256 threads, 8x4 micro-tile, float4 LDS.
// ---------------------------------------------------------------------------
__device__ __forceinline__
void gemm_body(const float* __restrict__ A,
               const float* __restrict__ W,
               const float* __restrict__ bias,
               float* __restrict__ C,
               int M, int N, int K)
{
    __shared__ float As[16][128];      // K-major
    __shared__ float Bs[16][64];

    const int tid = threadIdx.x;
    const int tx  = tid & 15;          // 4 cols  -> tx*4
    const int ty  = tid >> 4;          // 8 rows  -> ty*8
    const int r0  = blockIdx.y * 128;
    const int c0  = blockIdx.x * 64;

    float acc[8][4];
#pragma unroll
    for (int i = 0; i < 8; i++)
#pragma unroll
        for (int j = 0; j < 4; j++) acc[i][j] = 0.f;

    const int a_row = tid >> 1;            // 0..127
    const int a_col = (tid & 1) * 8;       // 0 or 8
    const int w_j   = tid & 63;
    const int w_kk  = (tid >> 6) * 4;

    for (int k0 = 0; k0 < K; k0 += 16) {
        const float4 av0 = *reinterpret_cast<const float4*>(
            &A[(size_t)(r0 + a_row) * K + k0 + a_col]);
        const float4 av1 = *reinterpret_cast<const float4*>(
            &A[(size_t)(r0 + a_row) * K + k0 + a_col + 4]);
        As[a_col + 0][a_row] = av0.x;
        As[a_col + 1][a_row] = av0.y;
        As[a_col + 2][a_row] = av0.z;
        As[a_col + 3][a_row] = av0.w;
        As[a_col + 4][a_row] = av1.x;
        As[a_col + 5][a_row] = av1.y;
        As[a_col + 6][a_row] = av1.z;
        As[a_col + 7][a_row] = av1.w;
        const float4 wv = *reinterpret_cast<const float4*>(
            &W[(size_t)(c0 + w_j) * K + k0 + w_kk]);
        Bs[w_kk + 0][w_j] = wv.x;
        Bs[w_kk + 1][w_j] = wv.y;
        Bs[w_kk + 2][w_j] = wv.z;
        Bs[w_kk + 3][w_j] = wv.w;
        __syncthreads();

#pragma unroll
        for (int kk = 0; kk < 16; kk++) {
            const float4 a0 = *reinterpret_cast<const float4*>(&As[kk][ty * 8]);
            const float4 a1 = *reinterpret_cast<const float4*>(&As[kk][ty * 8 + 4]);
            const float4 b  = *reinterpret_cast<const float4*>(&Bs[kk][tx * 4]);
            const float ar[8] = {a0.x, a0.y, a0.z, a0.w, a1.x, a1.y, a1.z, a1.w};
            const float br[4] = {b.x, b.y, b.z, b.w};
#pragma unroll
            for (int i = 0; i < 8; i++)
#pragma unroll
                for (int j = 0; j < 4; j++)
                    acc[i][j] += ar[i] * br[j];
        }
        __syncthreads();
    }

    const float4 bv = *reinterpret_cast<const float4*>(&bias[c0 + tx * 4]);
#pragma unroll
    for (int i = 0; i < 8; i++) {
        const size_t row = (size_t)(r0 + ty * 8 + i);
        float4 o;
        o.x = acc[i][0] + bv.x;
        o.y = acc[i][1] + bv.y;
        o.z = acc[i][2] + bv.z;
        o.w = acc[i][3] + bv.w;
        *reinterpret_cast<float4*>(&C[row * N + c0 + tx * 4]) = o;
    }
}

__global__ __launch_bounds__(256)
void qkv_gemm_kernel(const float* __restrict__ x,
                     const float* __restrict__ qkv_w,
                     const float* __restrict__ qkv_b)
{
    gemm_body(x, qkv_w, qkv_b, g_qkv, M_ROWS, QKV_N, DIM);
}

__global__ __launch_bounds__(256)
void proj_gemm_kernel(const float* __restrict__ proj_w,
                      const float* __restrict__ proj_b,
                      float* __restrict__ out)
{
    gemm_body(g_ctx, proj_w, proj_b, out, M_ROWS, DIM, DIM);
}

// ---------------------------------------------------------------------------
// Fused attention: one block per (window b, head h).
// k stored transposed-by-chunk (ksT4[c][j]) so the q.k loop is conflict-free.
// ---------------------------------------------------------------------------
__global__ __launch_bounds__(256)
void attn_kernel(float* __restrict__ attn_out, int write_attn)
{
    const int bh = blockIdx.x;
    const int b  = bh / NHEAD;
    const int h  = bh % NHEAD;
    const int tid = threadIdx.x;
    const int mb = b % NWIN;

    __shared__ float4 qs[NTOK * 8];      // [i][c]
    __shared__ float4 ksT4[8 * NTOK];    // [c][j]  <- transposed
    __shared__ float4 vs[NTOK * 8];      // [j][d4]
    __shared__ float  s[NTOK * 56];

    const size_t row0 = (size_t)b * NTOK;
    const int qoff = h * HDIM;
    const float scale = 0.1767766952966369f;  // 1/sqrt(32)

    // load q,k,v as float4 (q pre-scaled; k transposed into [c][j])
    for (int e = tid; e < NTOK * 8; e += 256) {
        const int i = e >> 3, c = e & 7;
        const size_t base = (row0 + i) * QKV_N + qoff + c * 4;
        float4 qv = *reinterpret_cast<const float4*>(&g_qkv[base]);
        qv.x *= scale; qv.y *= scale; qv.z *= scale; qv.w *= scale;
        qs[e] = qv;
        ksT4[c * NTOK + i] = *reinterpret_cast<const float4*>(&g_qkv[base + DIM]);
        vs[e] = *reinterpret_cast<const float4*>(&g_qkv[base + 2 * DIM]);
    }
    __syncthreads();

    // scores: s[i][j] = q_i . k_j + bm[e]
    // lanes have consecutive j -> ksT4 reads are consecutive float4s (no conflicts),
    // qs reads are broadcast.
    const float* bm = &g_bm[(size_t)(mb * NHEAD + h) * NN];
    for (int e = tid; e < NN; e += 256) {
        const int i = e / NTOK, j = e - i * NTOK;
        float dot = 0.f;
#pragma unroll
        for (int c = 0; c < 8; c++) {
            const float4 qv = qs[i * 8 + c];
            const float4 kv = ksT4[c * NTOK + j];
            dot += qv.x * kv.x + qv.y * kv.y + qv.z * kv.z + qv.w * kv.w;
        }
        s[i * 56 + j] = dot + bm[e];
    }
    __syncthreads();

    // softmax: quad (4 threads) per row. Shuffles executed warp-uniformly;
    // only smem accesses are guarded (avoids divergent-shuffle deadlock).
    {
        const int row = tid >> 2;
        const int q4  = tid & 3;
        const bool act = (row < NTOK);
        float* rowp = &s[(act ? row : 0) * 56];
        float mx = -1e30f;
        if (act) for (int j = q4; j < NTOK; j += 4) mx = fmaxf(mx, rowp[j]);
        mx = fmaxf(mx, __shfl_xor_sync(0xffffffffu, mx, 1));
        mx = fmaxf(mx, __shfl_xor_sync(0xffffffffu, mx, 2));
        float sum = 0.f;
        if (act) {
            for (int j = q4; j < NTOK; j += 4) {
                const float ev = __expf(rowp[j] - mx);
                rowp[j] = ev;
                sum += ev;
            }
        }
        sum += __shfl_xor_sync(0xffffffffu, sum, 1);
        sum += __shfl_xor_sync(0xffffffffu, sum, 2);
        if (act) {
            const float inv = 1.f / sum;
            for (int j = q4; j < NTOK; j += 4) rowp[j] *= inv;
        }
    }
    __syncthreads();

    if (write_attn) {
        float* ao = &attn_out[(size_t)bh * NN];
        for (int e = tid; e < NN; e += 256) {
            const int i = e / NTOK, j = e - i * NTOK;
            ao[e] = s[i * 56 + j];
        }
    }

    // out = s @ v : thread handles (i, d4) float4; vs reads conflict-free,
    // s reads broadcast.
    for (int e = tid; e < NTOK * 8; e += 256) {
        const int i = e >> 3, d4 = e & 7;
        float4 acc = make_float4(0.f, 0.f, 0.f, 0.f);
        const float* srow = &s[i * 56];
#pragma unroll
        for (int j = 0; j < NTOK; j++) {
            const float p = srow[j];
            const float4 vv = vs[j * 8 + d4];
            acc.x += p * vv.x;
            acc.y += p * vv.y;
            acc.z += p * vv.z;
            acc.w += p * vv.w;
        }
        *reinterpret_cast<float4*>(&g_ctx[(row0 + i) * DIM + qoff + d4 * 4]) = acc;
    }
}

extern "C" void kernel_launch(void* const* d_in, const int* in_sizes, int n_in,
                              void* d_out, int out_size)
{
    const float* x      = (const float*)d_in[0];
    const float* mask   = (const float*)d_in[1];
    const float* qkv_w  = (const float*)d_in[2];
    const float* qkv_b  = (const float*)d_in[3];
    const float* proj_w = (const float*)d_in[4];
    const float* proj_b = (const float*)d_in[5];
    const float* rpb    = (const float*)d_in[6];
    const int*   relidx = (const int*)d_in[7];
    float* out = (float*)d_out;

    const long out_elems  = (long)M_ROWS * DIM;                 // 38,535,168
    const long attn_elems = (long)B_TOT * NHEAD * NN;           // 59,006,976
    const int write_attn = ((long)out_size >= out_elems + attn_elems) ? 1 : 0;
    float* attn_out = out + out_elems;

    // 0) bias+mask table
    bm_kernel<<<NWIN * NHEAD, 256>>>(mask, rpb, relidx);

    // 1) QKV GEMM: [200704,192] @ [192,576]
    qkv_gemm_kernel<<<dim3(QKV_N / 64, M_ROWS / 128), 256>>>(x, qkv_w, qkv_b);

    // 2) fused window attention
    attn_kernel<<<B_TOT * NHEAD, 256>>>(attn_out, write_attn);

    // 3) projection: [200704,192] @ [192,192]
    proj_gemm_kernel<<<dim3(DIM / 64, M_ROWS / 128), 256>>>(proj_w, proj_b, out);
}

// round 6
// speedup vs baseline: 2.9661x; 1.2610x over previous
#include <cuda_runtime.h>
#include <math.h>

#define B_TOT   4096
#define NWIN    64
#define NTOK    49
#define DIM     192
#define NHEAD   6
#define HDIM    32
#define M_ROWS  (B_TOT * NTOK)     /* 200704 */
#define QKV_N   576
#define NN      (NTOK * NTOK)      /* 2401 */

// Scratch (no cudaMalloc allowed); referenced directly from kernels.
__device__ float g_qkv[(size_t)M_ROWS * QKV_N];          // 462 MB
__device__ float g_ctx[(size_t)M_ROWS * DIM];            // 154 MB
__device__ float g_bm[(size_t)NWIN * NHEAD * NN];        // 3.7 MB bias+mask

// ---------------------------------------------------------------------------
// Precompute bm[(mb*NHEAD+h)][e] = rpb[rel_idx[e]*NHEAD+h] + mask[mb][e]
// ---------------------------------------------------------------------------
__global__ __launch_bounds__(256)
void bm_kernel(const float* __restrict__ mask,
               const float* __restrict__ rpb_table,
               const int*   __restrict__ rel_idx)
{
    const int mb = blockIdx.x / NHEAD;
    const int h  = blockIdx.x % NHEAD;
    float* dst = &g_bm[(size_t)blockIdx.x * NN];
    const float* msk = &mask[(size_t)mb * NN];
    for (int e = threadIdx.x; e < NN; e += 256)
        dst[e] = rpb_table[rel_idx[e] * NHEAD + h] + msk[e];
}

// ---------------------------------------------------------------------------
// fp32 GEMM: C[M,N] = A[M,K] @ W^T + bias, W row-major [N,K]
// BM=256, BN=64, BK=16, 256 threads, 8x8 micro-tile (split row/col groups).
// 4 LDS.128 per 64 FMA -> FMA-bound, conflict-free.
// ---------------------------------------------------------------------------
__device__ __forceinline__
void gemm_body(const float* __restrict__ A,
               const float* __restrict__ W,
               const float* __restrict__ bias,
               float* __restrict__ C,
               int M, int N, int K)
{
    __shared__ float As[16][256];      // K-major
    __shared__ float Bs[16][64];

    const int tid = threadIdx.x;
    const int tx  = tid & 7;           // col groups: tx*4 and 32+tx*4
    const int ty  = tid >> 3;          // row groups: ty*4 and 128+ty*4 (ty 0..31)
    const int r0  = blockIdx.y * 256;
    const int c0  = blockIdx.x * 64;

    float acc[8][8];
#pragma unroll
    for (int i = 0; i < 8; i++)
#pragma unroll
        for (int j = 0; j < 8; j++) acc[i][j] = 0.f;

    const int w_j  = tid & 63;
    const int w_kk = (tid >> 6) * 4;

    for (int k0 = 0; k0 < K; k0 += 16) {
        // A tile: each thread loads one full row (16 floats) and transposes
        {
            const float* ap = &A[(size_t)(r0 + tid) * K + k0];
            const float4 a0 = *reinterpret_cast<const float4*>(ap);
            const float4 a1 = *reinterpret_cast<const float4*>(ap + 4);
            const float4 a2 = *reinterpret_cast<const float4*>(ap + 8);
            const float4 a3 = *reinterpret_cast<const float4*>(ap + 12);
            As[ 0][tid] = a0.x; As[ 1][tid] = a0.y; As[ 2][tid] = a0.z; As[ 3][tid] = a0.w;
            As[ 4][tid] = a1.x; As[ 5][tid] = a1.y; As[ 6][tid] = a1.z; As[ 7][tid] = a1.w;
            As[ 8][tid] = a2.x; As[ 9][tid] = a2.y; As[10][tid] = a2.z; As[11][tid] = a2.w;
            As[12][tid] = a3.x; As[13][tid] = a3.y; As[14][tid] = a3.z; As[15][tid] = a3.w;
        }
        // W tile
        {
            const float4 wv = *reinterpret_cast<const float4*>(
                &W[(size_t)(c0 + w_j) * K + k0 + w_kk]);
            Bs[w_kk + 0][w_j] = wv.x;
            Bs[w_kk + 1][w_j] = wv.y;
            Bs[w_kk + 2][w_j] = wv.z;
            Bs[w_kk + 3][w_j] = wv.w;
        }
        __syncthreads();

#pragma unroll
        for (int kk = 0; kk < 16; kk++) {
            const float4 a0 = *reinterpret_cast<const float4*>(&As[kk][ty * 4]);
            const float4 a1 = *reinterpret_cast<const float4*>(&As[kk][128 + ty * 4]);
            const float4 b0 = *reinterpret_cast<const float4*>(&Bs[kk][tx * 4]);
            const float4 b1 = *reinterpret_cast<const float4*>(&Bs[kk][32 + tx * 4]);
            const float ar[8] = {a0.x, a0.y, a0.z, a0.w, a1.x, a1.y, a1.z, a1.w};
            const float br[8] = {b0.x, b0.y, b0.z, b0.w, b1.x, b1.y, b1.z, b1.w};
#pragma unroll
            for (int i = 0; i < 8; i++)
#pragma unroll
                for (int j = 0; j < 8; j++)
                    acc[i][j] += ar[i] * br[j];
        }
        __syncthreads();
    }

    const float4 bv0 = *reinterpret_cast<const float4*>(&bias[c0 + tx * 4]);
    const float4 bv1 = *reinterpret_cast<const float4*>(&bias[c0 + 32 + tx * 4]);
    const float bb[8] = {bv0.x, bv0.y, bv0.z, bv0.w, bv1.x, bv1.y, bv1.z, bv1.w};
#pragma unroll
    for (int i = 0; i < 8; i++) {
        const int row = (i < 4) ? (ty * 4 + i) : (128 + ty * 4 + i - 4);
        float* cp = &C[(size_t)(r0 + row) * N + c0];
        float4 o0, o1;
        o0.x = acc[i][0] + bb[0]; o0.y = acc[i][1] + bb[1];
        o0.z = acc[i][2] + bb[2]; o0.w = acc[i][3] + bb[3];
        o1.x = acc[i][4] + bb[4]; o1.y = acc[i][5] + bb[5];
        o1.z = acc[i][6] + bb[6]; o1.w = acc[i][7] + bb[7];
        *reinterpret_cast<float4*>(&cp[tx * 4])      = o0;
        *reinterpret_cast<float4*>(&cp[32 + tx * 4]) = o1;
    }
}

__global__ __launch_bounds__(256)
void qkv_gemm_kernel(const float* __restrict__ x,
                     const float* __restrict__ qkv_w,
                     const float* __restrict__ qkv_b)
{
    gemm_body(x, qkv_w, qkv_b, g_qkv, M_ROWS, QKV_N, DIM);
}

__global__ __launch_bounds__(256)
void proj_gemm_kernel(const float* __restrict__ proj_w,
                      const float* __restrict__ proj_b,
                      float* __restrict__ out)
{
    gemm_body(g_ctx, proj_w, proj_b, out, M_ROWS, DIM, DIM);
}

// ---------------------------------------------------------------------------
// Fused attention: one block per (window b, head h).
// Score phase: 4x4 register tiles (13x13 tile grid). PV: 2-row tiles.
// ---------------------------------------------------------------------------
#define QPAD 52                 /* padded token rows for q/k (multiple of 4) */

__global__ __launch_bounds__(256)
void attn_kernel(float* __restrict__ attn_out, int write_attn)
{
    const int bh = blockIdx.x;
    const int b  = bh / NHEAD;
    const int h  = bh % NHEAD;
    const int tid = threadIdx.x;
    const int mb = b % NWIN;

    __shared__ float4 qs[QPAD * 9];      // [i][c], row stride 9 (conflict pad)
    __shared__ float4 ksT4[8 * QPAD];    // [c][j]
    __shared__ float4 vs[NTOK * 8];      // [j][d4]
    __shared__ float  s[NTOK * 56];

    const size_t row0 = (size_t)b * NTOK;
    const int qoff = h * HDIM;
    const float scale = 0.1767766952966369f;  // 1/sqrt(32)

    // load q (scaled), k (transposed), v; zero pad rows 49..51
    for (int e = tid; e < QPAD * 8; e += 256) {
        const int i = e >> 3, c = e & 7;
        if (i < NTOK) {
            const size_t base = (row0 + i) * QKV_N + qoff + c * 4;
            float4 qv = *reinterpret_cast<const float4*>(&g_qkv[base]);
            qv.x *= scale; qv.y *= scale; qv.z *= scale; qv.w *= scale;
            qs[i * 9 + c] = qv;
            ksT4[c * QPAD + i] = *reinterpret_cast<const float4*>(&g_qkv[base + DIM]);
            vs[i * 8 + c] = *reinterpret_cast<const float4*>(&g_qkv[base + 2 * DIM]);
        } else {
            const float4 z = make_float4(0.f, 0.f, 0.f, 0.f);
            qs[i * 9 + c] = z;
            ksT4[c * QPAD + i] = z;
        }
    }
    __syncthreads();

    // scores: 4x4 tiles; 13x13 = 169 tiles, one per thread
    const float* bm = &g_bm[(size_t)(mb * NHEAD + h) * NN];
    if (tid < 169) {
        const int ti = tid / 13, tj = tid % 13;
        const int i0 = ti * 4, j0 = tj * 4;
        float acc[4][4];
#pragma unroll
        for (int u = 0; u < 4; u++)
#pragma unroll
            for (int v = 0; v < 4; v++) acc[u][v] = 0.f;
#pragma unroll
        for (int c = 0; c < 8; c++) {
            float4 qv[4], kv[4];
#pragma unroll
            for (int u = 0; u < 4; u++) qv[u] = qs[(i0 + u) * 9 + c];
#pragma unroll
            for (int v = 0; v < 4; v++) kv[v] = ksT4[c * QPAD + j0 + v];
#pragma unroll
            for (int u = 0; u < 4; u++)
#pragma unroll
                for (int v = 0; v < 4; v++)
                    acc[u][v] += qv[u].x * kv[v].x + qv[u].y * kv[v].y
                               + qv[u].z * kv[v].z + qv[u].w * kv[v].w;
        }
#pragma unroll
        for (int u = 0; u < 4; u++) {
            const int i = i0 + u;
            if (i < NTOK) {
#pragma unroll
                for (int v = 0; v < 4; v++) {
                    const int j = j0 + v;
                    if (j < NTOK)
                        s[i * 56 + j] = acc[u][v] + bm[i * NTOK + j];
                }
            }
        }
    }
    __syncthreads();

    // softmax: quad per row; shuffles warp-uniform (no divergence)
    {
        const int row = tid >> 2;
        const int q4  = tid & 3;
        const bool act = (row < NTOK);
        float* rowp = &s[(act ? row : 0) * 56];
        float mx = -1e30f;
        if (act) for (int j = q4; j < NTOK; j += 4) mx = fmaxf(mx, rowp[j]);
        mx = fmaxf(mx, __shfl_xor_sync(0xffffffffu, mx, 1));
        mx = fmaxf(mx, __shfl_xor_sync(0xffffffffu, mx, 2));
        float sum = 0.f;
        if (act) {
            for (int j = q4; j < NTOK; j += 4) {
                const float ev = __expf(rowp[j] - mx);
                rowp[j] = ev;
                sum += ev;
            }
        }
        sum += __shfl_xor_sync(0xffffffffu, sum, 1);
        sum += __shfl_xor_sync(0xffffffffu, sum, 2);
        if (act) {
            const float inv = 1.f / sum;
            for (int j = q4; j < NTOK; j += 4) rowp[j] *= inv;
        }
    }
    __syncthreads();

    if (write_attn) {
        float* ao = &attn_out[(size_t)bh * NN];
        for (int e = tid; e < NN; e += 256) {
            const int i = e / NTOK, j = e - i * NTOK;
            ao[e] = s[i * 56 + j];
        }
    }

    // out = s @ v : thread handles 2 rows x one d4; v reads broadcast
    if (tid < 200) {
        const int ip = tid >> 3, d4 = tid & 7;   // ip 0..24
        const int i0 = ip * 2;
        float4 a0 = make_float4(0.f, 0.f, 0.f, 0.f);
        float4 a1 = make_float4(0.f, 0.f, 0.f, 0.f);
        const float* s0 = &s[i0 * 56];
        const bool two = (i0 + 1 < NTOK);
#pragma unroll
        for (int j = 0; j < NTOK; j++) {
            const float4 vv = vs[j * 8 + d4];
            const float p0 = s0[j];
            a0.x += p0 * vv.x; a0.y += p0 * vv.y;
            a0.z += p0 * vv.z; a0.w += p0 * vv.w;
            const float p1 = two ? s0[56 + j] : 0.f;
            a1.x += p1 * vv.x; a1.y += p1 * vv.y;
            a1.z += p1 * vv.z; a1.w += p1 * vv.w;
        }
        *reinterpret_cast<float4*>(&g_ctx[(row0 + i0) * DIM + qoff + d4 * 4]) = a0;
        if (two)
            *reinterpret_cast<float4*>(&g_ctx[(row0 + i0 + 1) * DIM + qoff + d4 * 4]) = a1;
    }
}

extern "C" void kernel_launch(void* const* d_in, const int* in_sizes, int n_in,
                              void* d_out, int out_size)
{
    const float* x      = (const float*)d_in[0];
    const float* mask   = (const float*)d_in[1];
    const float* qkv_w  = (const float*)d_in[2];
    const float* qkv_b  = (const float*)d_in[3];
    const float* proj_w = (const float*)d_in[4];
    const float* proj_b = (const float*)d_in[5];
    const float* rpb    = (const float*)d_in[6];
    const int*   relidx = (const int*)d_in[7];
    float* out = (float*)d_out;

    const long out_elems  = (long)M_ROWS * DIM;                 // 38,535,168
    const long attn_elems = (long)B_TOT * NHEAD * NN;           // 59,006,976
    const int write_attn = ((long)out_size >= out_elems + attn_elems) ? 1 : 0;
    float* attn_out = out + out_elems;

    // 0) bias+mask table
    bm_kernel<<<NWIN * NHEAD, 256>>>(mask, rpb, relidx);

    // 1) QKV GEMM: [200704,192] @ [192,576]
    qkv_gemm_kernel<<<dim3(QKV_N / 64, M_ROWS / 256), 256>>>(x, qkv_w, qkv_b);

    // 2) fused window attention
    attn_kernel<<<B_TOT * NHEAD, 256>>>(attn_out, write_attn);

    // 3) projection: [200704,192] @ [192,192]
    proj_gemm_kernel<<<dim3(DIM / 64, M_ROWS / 256), 256>>>(proj_w, proj_b, out);
}

// round 7
// speedup vs baseline: 3.0774x; 1.0375x over previous
#include <cuda_runtime.h>
#include <math.h>
#include <stdint.h>

#define B_TOT   4096
#define NWIN    64
#define NTOK    49
#define DIM     192
#define NHEAD   6
#define HDIM    32
#define M_ROWS  (B_TOT * NTOK)     /* 200704 */
#define QKV_N   576
#define NN      (NTOK * NTOK)      /* 2401 */

// Scratch (no cudaMalloc allowed); referenced directly from kernels.
__device__ float g_qkv[(size_t)M_ROWS * QKV_N];          // 462 MB
__device__ float g_ctx[(size_t)M_ROWS * DIM];            // 154 MB
__device__ float g_bm[(size_t)NWIN * NHEAD * NN];        // 3.7 MB bias+mask

// ---------------------------------------------------------------------------
// Precompute bm[(mb*NHEAD+h)][e] = rpb[rel_idx[e]*NHEAD+h] + mask[mb][e]
// ---------------------------------------------------------------------------
__global__ __launch_bounds__(256)
void bm_kernel(const float* __restrict__ mask,
               const float* __restrict__ rpb_table,
               const int*   __restrict__ rel_idx)
{
    const int mb = blockIdx.x / NHEAD;
    const int h  = blockIdx.x % NHEAD;
    float* dst = &g_bm[(size_t)blockIdx.x * NN];
    const float* msk = &mask[(size_t)mb * NN];
    for (int e = threadIdx.x; e < NN; e += 256)
        dst[e] = rpb_table[rel_idx[e] * NHEAD + h] + msk[e];
}

// ---------------------------------------------------------------------------
// TF32 tensor-core GEMM with 3xTF32 split accuracy.
// C[M,N] = A[M,K] @ W^T + bias, W row-major [N,K] (== B col-major k x n).
// BM=128, BN=64, BK=16, 256 threads (8 warps, 4x2 grid of 32x32 warp tiles).
// ---------------------------------------------------------------------------
__device__ __forceinline__ uint32_t cvt_tf32(float f) {
    uint32_t u;
    asm("cvt.rna.tf32.f32 %0, %1;" : "=r"(u) : "f"(f));
    return u;
}

__device__ __forceinline__ void mma_tf32(float* d, const uint32_t* a, const uint32_t* b) {
    asm volatile(
        "mma.sync.aligned.m16n8k8.row.col.f32.tf32.tf32.f32 "
        "{%0,%1,%2,%3}, {%4,%5,%6,%7}, {%8,%9}, {%0,%1,%2,%3};"
        : "+f"(d[0]), "+f"(d[1]), "+f"(d[2]), "+f"(d[3])
        : "r"(a[0]), "r"(a[1]), "r"(a[2]), "r"(a[3]), "r"(b[0]), "r"(b[1]));
}

#define SA 20   /* smem row stride for A/B tiles (conflict-free for frag loads) */

__global__ __launch_bounds__(256)
void gemm_tf32_kernel(const float* __restrict__ A,
                      const float* __restrict__ W,
                      const float* __restrict__ bias,
                      float* __restrict__ C,
                      int M, int N, int K)
{
    __shared__ uint32_t Ah[128 * SA];
    __shared__ uint32_t Al[128 * SA];
    __shared__ uint32_t Bh[64 * SA];
    __shared__ uint32_t Bl[64 * SA];

    const int tid  = threadIdx.x;
    const int warp = tid >> 5;
    const int lane = tid & 31;
    const int wm   = warp >> 1;        // 0..3  -> m offset wm*32
    const int wn   = warp & 1;         // 0..1  -> n offset wn*32
    const int lr   = lane >> 2;        // 0..7
    const int lc   = lane & 3;         // 0..3
    const int r0   = blockIdx.y * 128;
    const int c0   = blockIdx.x * 64;

    // global load indices
    const int ar = tid >> 1;           // A row 0..127
    const int ac = (tid & 1) * 8;      // A col 0 or 8
    const int br = tid >> 2;           // B row 0..63
    const int bc = (tid & 3) * 4;      // B col 0,4,8,12

    const float* Ag = &A[(size_t)(r0 + ar) * K + ac];
    const float* Wg = &W[(size_t)(c0 + br) * K + bc];

    float acc[2][4][4];
#pragma unroll
    for (int mt = 0; mt < 2; mt++)
#pragma unroll
        for (int nt = 0; nt < 4; nt++)
#pragma unroll
            for (int r = 0; r < 4; r++) acc[mt][nt][r] = 0.f;

    // prologue prefetch
    float ap[8], bp[4];
    {
        const float4 a0 = *reinterpret_cast<const float4*>(Ag);
        const float4 a1 = *reinterpret_cast<const float4*>(Ag + 4);
        ap[0]=a0.x; ap[1]=a0.y; ap[2]=a0.z; ap[3]=a0.w;
        ap[4]=a1.x; ap[5]=a1.y; ap[6]=a1.z; ap[7]=a1.w;
        const float4 b0 = *reinterpret_cast<const float4*>(Wg);
        bp[0]=b0.x; bp[1]=b0.y; bp[2]=b0.z; bp[3]=b0.w;
    }

    for (int k0 = 0; k0 < K; k0 += 16) {
        // store (split hi/lo) to smem
#pragma unroll
        for (int i = 0; i < 8; i++) {
            const uint32_t h = cvt_tf32(ap[i]);
            Ah[ar * SA + ac + i] = h;
            Al[ar * SA + ac + i] = cvt_tf32(ap[i] - __uint_as_float(h));
        }
#pragma unroll
        for (int i = 0; i < 4; i++) {
            const uint32_t h = cvt_tf32(bp[i]);
            Bh[br * SA + bc + i] = h;
            Bl[br * SA + bc + i] = cvt_tf32(bp[i] - __uint_as_float(h));
        }
        __syncthreads();

        // prefetch next tile
        if (k0 + 16 < K) {
            const float4 a0 = *reinterpret_cast<const float4*>(Ag + k0 + 16);
            const float4 a1 = *reinterpret_cast<const float4*>(Ag + k0 + 20);
            ap[0]=a0.x; ap[1]=a0.y; ap[2]=a0.z; ap[3]=a0.w;
            ap[4]=a1.x; ap[5]=a1.y; ap[6]=a1.z; ap[7]=a1.w;
            const float4 b0 = *reinterpret_cast<const float4*>(Wg + k0 + 16);
            bp[0]=b0.x; bp[1]=b0.y; bp[2]=b0.z; bp[3]=b0.w;
        }

        // compute: 2 k-steps of k8
#pragma unroll
        for (int kk = 0; kk < 2; kk++) {
            const int kb = kk * 8;
            uint32_t afh[2][4], afl[2][4], bfh[4][2], bfl[4][2];
#pragma unroll
            for (int mt = 0; mt < 2; mt++) {
                const int base = (wm * 32 + mt * 16 + lr) * SA + kb + lc;
                afh[mt][0] = Ah[base];
                afh[mt][1] = Ah[base + 8 * SA];
                afh[mt][2] = Ah[base + 4];
                afh[mt][3] = Ah[base + 8 * SA + 4];
                afl[mt][0] = Al[base];
                afl[mt][1] = Al[base + 8 * SA];
                afl[mt][2] = Al[base + 4];
                afl[mt][3] = Al[base + 8 * SA + 4];
            }
#pragma unroll
            for (int nt = 0; nt < 4; nt++) {
                const int nb = (wn * 32 + nt * 8 + lr) * SA + kb + lc;
                bfh[nt][0] = Bh[nb];
                bfh[nt][1] = Bh[nb + 4];
                bfl[nt][0] = Bl[nb];
                bfl[nt][1] = Bl[nb + 4];
            }
#pragma unroll
            for (int mt = 0; mt < 2; mt++)
#pragma unroll
                for (int nt = 0; nt < 4; nt++) {
                    mma_tf32(acc[mt][nt], afl[mt], bfh[nt]);   // lo*hi
                    mma_tf32(acc[mt][nt], afh[mt], bfl[nt]);   // hi*lo
                    mma_tf32(acc[mt][nt], afh[mt], bfh[nt]);   // hi*hi
                }
        }
        __syncthreads();
    }

    // epilogue
#pragma unroll
    for (int mt = 0; mt < 2; mt++) {
        const int row = r0 + wm * 32 + mt * 16 + lr;
#pragma unroll
        for (int nt = 0; nt < 4; nt++) {
            const int col = c0 + wn * 32 + nt * 8 + lc * 2;
            const float b0v = bias[col], b1v = bias[col + 1];
            float2 s0, s1;
            s0.x = acc[mt][nt][0] + b0v; s0.y = acc[mt][nt][1] + b1v;
            s1.x = acc[mt][nt][2] + b0v; s1.y = acc[mt][nt][3] + b1v;
            *reinterpret_cast<float2*>(&C[(size_t)row * N + col])       = s0;
            *reinterpret_cast<float2*>(&C[(size_t)(row + 8) * N + col]) = s1;
        }
    }
}

__global__ __launch_bounds__(256)
void qkv_gemm_kernel(const float* __restrict__ x,
                     const float* __restrict__ qkv_w,
                     const float* __restrict__ qkv_b)
{
    // forward to device GEMM body via direct code (separate launch wrapper)
    // (implemented as a call: identical signature usage)
    // NOTE: actual work is done by gemm_tf32_kernel launched from host.
}

// ---------------------------------------------------------------------------
// Fused attention (unchanged from R6): one block per (window b, head h).
// ---------------------------------------------------------------------------
#define QPAD 52

__global__ __launch_bounds__(256)
void attn_kernel(float* __restrict__ attn_out, int write_attn)
{
    const int bh = blockIdx.x;
    const int b  = bh / NHEAD;
    const int h  = bh % NHEAD;
    const int tid = threadIdx.x;
    const int mb = b % NWIN;

    __shared__ float4 qs[QPAD * 9];
    __shared__ float4 ksT4[8 * QPAD];
    __shared__ float4 vs[NTOK * 8];
    __shared__ float  s[NTOK * 56];

    const size_t row0 = (size_t)b * NTOK;
    const int qoff = h * HDIM;
    const float scale = 0.1767766952966369f;

    for (int e = tid; e < QPAD * 8; e += 256) {
        const int i = e >> 3, c = e & 7;
        if (i < NTOK) {
            const size_t base = (row0 + i) * QKV_N + qoff + c * 4;
            float4 qv = *reinterpret_cast<const float4*>(&g_qkv[base]);
            qv.x *= scale; qv.y *= scale; qv.z *= scale; qv.w *= scale;
            qs[i * 9 + c] = qv;
            ksT4[c * QPAD + i] = *reinterpret_cast<const float4*>(&g_qkv[base + DIM]);
            vs[i * 8 + c] = *reinterpret_cast<const float4*>(&g_qkv[base + 2 * DIM]);
        } else {
            const float4 z = make_float4(0.f, 0.f, 0.f, 0.f);
            qs[i * 9 + c] = z;
            ksT4[c * QPAD + i] = z;
        }
    }
    __syncthreads();

    const float* bm = &g_bm[(size_t)(mb * NHEAD + h) * NN];
    if (tid < 169) {
        const int ti = tid / 13, tj = tid % 13;
        const int i0 = ti * 4, j0 = tj * 4;
        float acc[4][4];
#pragma unroll
        for (int u = 0; u < 4; u++)
#pragma unroll
            for (int v = 0; v < 4; v++) acc[u][v] = 0.f;
#pragma unroll
        for (int c = 0; c < 8; c++) {
            float4 qv[4], kv[4];
#pragma unroll
            for (int u = 0; u < 4; u++) qv[u] = qs[(i0 + u) * 9 + c];
#pragma unroll
            for (int v = 0; v < 4; v++) kv[v] = ksT4[c * QPAD + j0 + v];
#pragma unroll
            for (int u = 0; u < 4; u++)
#pragma unroll
                for (int v = 0; v < 4; v++)
                    acc[u][v] += qv[u].x * kv[v].x + qv[u].y * kv[v].y
                               + qv[u].z * kv[v].z + qv[u].w * kv[v].w;
        }
#pragma unroll
        for (int u = 0; u < 4; u++) {
            const int i = i0 + u;
            if (i < NTOK) {
#pragma unroll
                for (int v = 0; v < 4; v++) {
                    const int j = j0 + v;
                    if (j < NTOK)
                        s[i * 56 + j] = acc[u][v] + bm[i * NTOK + j];
                }
            }
        }
    }
    __syncthreads();

    {
        const int row = tid >> 2;
        const int q4  = tid & 3;
        const bool act = (row < NTOK);
        float* rowp = &s[(act ? row : 0) * 56];
        float mx = -1e30f;
        if (act) for (int j = q4; j < NTOK; j += 4) mx = fmaxf(mx, rowp[j]);
        mx = fmaxf(mx, __shfl_xor_sync(0xffffffffu, mx, 1));
        mx = fmaxf(mx, __shfl_xor_sync(0xffffffffu, mx, 2));
        float sum = 0.f;
        if (act) {
            for (int j = q4; j < NTOK; j += 4) {
                const float ev = __expf(rowp[j] - mx);
                rowp[j] = ev;
                sum += ev;
            }
        }
        sum += __shfl_xor_sync(0xffffffffu, sum, 1);
        sum += __shfl_xor_sync(0xffffffffu, sum, 2);
        if (act) {
            const float inv = 1.f / sum;
            for (int j = q4; j < NTOK; j += 4) rowp[j] *= inv;
        }
    }
    __syncthreads();

    if (write_attn) {
        float* ao = &attn_out[(size_t)bh * NN];
        for (int e = tid; e < NN; e += 256) {
            const int i = e / NTOK, j = e - i * NTOK;
            ao[e] = s[i * 56 + j];
        }
    }

    if (tid < 200) {
        const int ip = tid >> 3, d4 = tid & 7;
        const int i0 = ip * 2;
        float4 a0 = make_float4(0.f, 0.f, 0.f, 0.f);
        float4 a1 = make_float4(0.f, 0.f, 0.f, 0.f);
        const float* s0 = &s[i0 * 56];
        const bool two = (i0 + 1 < NTOK);
#pragma unroll
        for (int j = 0; j < NTOK; j++) {
            const float4 vv = vs[j * 8 + d4];
            const float p0 = s0[j];
            a0.x += p0 * vv.x; a0.y += p0 * vv.y;
            a0.z += p0 * vv.z; a0.w += p0 * vv.w;
            const float p1 = two ? s0[56 + j] : 0.f;
            a1.x += p1 * vv.x; a1.y += p1 * vv.y;
            a1.z += p1 * vv.z; a1.w += p1 * vv.w;
        }
        *reinterpret_cast<float4*>(&g_ctx[(row0 + i0) * DIM + qoff + d4 * 4]) = a0;
        if (two)
            *reinterpret_cast<float4*>(&g_ctx[(row0 + i0 + 1) * DIM + qoff + d4 * 4]) = a1;
    }
}

// host-visible device pointers for the GEMM launches
__global__ void dummy_unused() {}

extern "C" void kernel_launch(void* const* d_in, const int* in_sizes, int n_in,
                              void* d_out, int out_size)
{
    const float* x      = (const float*)d_in[0];
    const float* mask   = (const float*)d_in[1];
    const float* qkv_w  = (const float*)d_in[2];
    const float* qkv_b  = (const float*)d_in[3];
    const float* proj_w = (const float*)d_in[4];
    const float* proj_b = (const float*)d_in[5];
    const float* rpb    = (const float*)d_in[6];
    const int*   relidx = (const int*)d_in[7];
    float* out = (float*)d_out;

    const long out_elems  = (long)M_ROWS * DIM;                 // 38,535,168
    const long attn_elems = (long)B_TOT * NHEAD * NN;           // 59,006,976
    const int write_attn = ((long)out_size >= out_elems + attn_elems) ? 1 : 0;
    float* attn_out = out + out_elems;

    // device scratch addresses via statically-known symbols: use kernels that
    // reference g_qkv/g_ctx directly is not possible for the generic GEMM, so
    // resolve once via cudaGetSymbolAddress is NOT capture-safe; instead use
    // constant device pointers computed here each call (pure host arithmetic).
    // cudaGetSymbolAddress is a pure host-side lookup (no stream op) and is
    // capture-safe in practice, but we avoid it: pass via kernel that derives
    // the pointer. Simplest robust path: small static host cache is forbidden
    // (determinism is unaffected, but avoid statics anyway) -> use
    // cudaGetSymbolAddress each call (host-only, no graph node).
    float *qkv_ptr = nullptr, *ctx_ptr = nullptr;
    cudaGetSymbolAddress((void**)&qkv_ptr, g_qkv);
    cudaGetSymbolAddress((void**)&ctx_ptr, g_ctx);

    // 0) bias+mask table
    bm_kernel<<<NWIN * NHEAD, 256>>>(mask, rpb, relidx);

    // 1) QKV GEMM: [200704,192] @ [192,576] (3xTF32 tensor cores)
    gemm_tf32_kernel<<<dim3(QKV_N / 64, M_ROWS / 128), 256>>>(
        x, qkv_w, qkv_b, qkv_ptr, M_ROWS, QKV_N, DIM);

    // 2) fused window attention
    attn_kernel<<<B_TOT * NHEAD, 256>>>(attn_out, write_attn);

    // 3) projection: [200704,192] @ [192,192] (3xTF32 tensor cores)
    gemm_tf32_kernel<<<dim3(DIM / 64, M_ROWS / 128), 256>>>(
        ctx_ptr, proj_w, proj_b, out, M_ROWS, DIM, DIM);
}

// round 9
// speedup vs baseline: 4.2422x; 1.3785x over previous
#include <cuda_runtime.h>
#include <cuda_bf16.h>
#include <math.h>
#include <stdint.h>

#define B_TOT   4096
#define NWIN    64
#define NTOK    49
#define DIM     192
#define NHEAD   6
#define HDIM    32
#define M_ROWS  (B_TOT * NTOK)     /* 200704 */
#define QKV_N   576
#define NN      (NTOK * NTOK)      /* 2401 */

// Scratch (no cudaMalloc allowed); referenced directly from kernels so that
// kernel_launch contains ONLY kernel launches (trivially graph-capturable).
__device__ float g_qkv[(size_t)M_ROWS * QKV_N];          // 462 MB
__device__ float g_ctx[(size_t)M_ROWS * DIM];            // 154 MB
__device__ float g_bm[(size_t)NWIN * NHEAD * NN];        // 3.7 MB bias+mask

// ---------------------------------------------------------------------------
// Precompute bm[(mb*NHEAD+h)][e] = rpb[rel_idx[e]*NHEAD+h] + mask[mb][e]
// ---------------------------------------------------------------------------
__global__ __launch_bounds__(256)
void bm_kernel(const float* __restrict__ mask,
               const float* __restrict__ rpb_table,
               const int*   __restrict__ rel_idx)
{
    const int mb = blockIdx.x / NHEAD;
    const int h  = blockIdx.x % NHEAD;
    float* dst = &g_bm[(size_t)blockIdx.x * NN];
    const float* msk = &mask[(size_t)mb * NN];
    for (int e = threadIdx.x; e < NN; e += 256)
        dst[e] = rpb_table[rel_idx[e] * NHEAD + h] + msk[e];
}

// ---------------------------------------------------------------------------
// bf16x3 tensor-core GEMM: C[M,N] = A[M,K] @ W^T + bias, W row-major [N,K].
// BM=128, BN=64, BK=16, 256 threads (8 warps, 4x2 grid of 32x32 warp tiles).
// Split a = a_h + a_l (bf16 each); C ≈ ah*bh + ah*bl + al*bh (fp32 acc).
// ---------------------------------------------------------------------------
__device__ __forceinline__ uint32_t pack_bf16x2(float x, float y) {
    __nv_bfloat162 t = __floats2bfloat162_rn(x, y);   // x -> low 16 bits
    return *reinterpret_cast<uint32_t*>(&t);
}

__device__ __forceinline__ void mma_bf16(float* d, const uint32_t* a, const uint32_t* b) {
    asm volatile(
        "mma.sync.aligned.m16n8k16.row.col.f32.bf16.bf16.f32 "
        "{%0,%1,%2,%3}, {%4,%5,%6,%7}, {%8,%9}, {%0,%1,%2,%3};"
        : "+f"(d[0]), "+f"(d[1]), "+f"(d[2]), "+f"(d[3])
        : "r"(a[0]), "r"(a[1]), "r"(a[2]), "r"(a[3]), "r"(b[0]), "r"(b[1]));
}

#define SW 12   /* smem row stride in 32-bit words (8 data + 4 pad): conflict-free */

__device__ __forceinline__
void gemm_bf16x3_body(const float* __restrict__ A,
                      const float* __restrict__ W,
                      const float* __restrict__ bias,
                      float* __restrict__ C,
                      int M, int N, int K)
{
    __shared__ uint32_t Ah[128 * SW];
    __shared__ uint32_t Al[128 * SW];
    __shared__ uint32_t Bh[64 * SW];
    __shared__ uint32_t Bl[64 * SW];

    const int tid  = threadIdx.x;
    const int warp = tid >> 5;
    const int lane = tid & 31;
    const int wm   = warp >> 1;        // 0..3 -> m offset wm*32
    const int wn   = warp & 1;         // 0..1 -> n offset wn*32
    const int lr   = lane >> 2;        // 0..7
    const int lc   = lane & 3;         // 0..3
    const int r0   = blockIdx.y * 128;
    const int c0   = blockIdx.x * 64;

    // global load indices
    const int ar = tid >> 1;           // A row 0..127
    const int ac = (tid & 1) * 8;      // A col 0 or 8
    const int br = tid >> 2;           // B row 0..63
    const int bc = (tid & 3) * 4;      // B col 0,4,8,12

    const float* Ag = &A[(size_t)(r0 + ar) * K + ac];
    const float* Wg = &W[(size_t)(c0 + br) * K + bc];

    float acc[2][4][4];
#pragma unroll
    for (int mt = 0; mt < 2; mt++)
#pragma unroll
        for (int nt = 0; nt < 4; nt++)
#pragma unroll
            for (int r = 0; r < 4; r++) acc[mt][nt][r] = 0.f;

    // prologue prefetch
    float ap[8], bp[4];
    {
        const float4 a0 = *reinterpret_cast<const float4*>(Ag);
        const float4 a1 = *reinterpret_cast<const float4*>(Ag + 4);
        ap[0]=a0.x; ap[1]=a0.y; ap[2]=a0.z; ap[3]=a0.w;
        ap[4]=a1.x; ap[5]=a1.y; ap[6]=a1.z; ap[7]=a1.w;
        const float4 b0 = *reinterpret_cast<const float4*>(Wg);
        bp[0]=b0.x; bp[1]=b0.y; bp[2]=b0.z; bp[3]=b0.w;
    }

    for (int k0 = 0; k0 < K; k0 += 16) {
        // split hi/lo, pack bf16x2, store to smem
#pragma unroll
        for (int i = 0; i < 4; i++) {
            const float f0 = ap[2 * i], f1 = ap[2 * i + 1];
            const float h0 = __bfloat162float(__float2bfloat16_rn(f0));
            const float h1 = __bfloat162float(__float2bfloat16_rn(f1));
            Ah[ar * SW + ac / 2 + i] = pack_bf16x2(h0, h1);
            Al[ar * SW + ac / 2 + i] = pack_bf16x2(f0 - h0, f1 - h1);
        }
#pragma unroll
        for (int i = 0; i < 2; i++) {
            const float f0 = bp[2 * i], f1 = bp[2 * i + 1];
            const float h0 = __bfloat162float(__float2bfloat16_rn(f0));
            const float h1 = __bfloat162float(__float2bfloat16_rn(f1));
            Bh[br * SW + bc / 2 + i] = pack_bf16x2(h0, h1);
            Bl[br * SW + bc / 2 + i] = pack_bf16x2(f0 - h0, f1 - h1);
        }
        __syncthreads();

        // prefetch next tile
        if (k0 + 16 < K) {
            const float4 a0 = *reinterpret_cast<const float4*>(Ag + k0 + 16);
            const float4 a1 = *reinterpret_cast<const float4*>(Ag + k0 + 20);
            ap[0]=a0.x; ap[1]=a0.y; ap[2]=a0.z; ap[3]=a0.w;
            ap[4]=a1.x; ap[5]=a1.y; ap[6]=a1.z; ap[7]=a1.w;
            const float4 b0 = *reinterpret_cast<const float4*>(Wg + k0 + 16);
            bp[0]=b0.x; bp[1]=b0.y; bp[2]=b0.z; bp[3]=b0.w;
        }

        // one m16n8k16 step covers the whole BK=16 tile
        uint32_t ah[2][4], al[2][4], bh[4][2], bl[4][2];
#pragma unroll
        for (int mt = 0; mt < 2; mt++) {
            const int base = (wm * 32 + mt * 16 + lr) * SW + lc;
            ah[mt][0] = Ah[base];
            ah[mt][1] = Ah[base + 8 * SW];
            ah[mt][2] = Ah[base + 4];
            ah[mt][3] = Ah[base + 8 * SW + 4];
            al[mt][0] = Al[base];
            al[mt][1] = Al[base + 8 * SW];
            al[mt][2] = Al[base + 4];
            al[mt][3] = Al[base + 8 * SW + 4];
        }
#pragma unroll
        for (int nt = 0; nt < 4; nt++) {
            const int nb = (wn * 32 + nt * 8 + lr) * SW + lc;
            bh[nt][0] = Bh[nb];
            bh[nt][1] = Bh[nb + 4];
            bl[nt][0] = Bl[nb];
            bl[nt][1] = Bl[nb + 4];
        }
#pragma unroll
        for (int mt = 0; mt < 2; mt++)
#pragma unroll
            for (int nt = 0; nt < 4; nt++) {
                mma_bf16(acc[mt][nt], ah[mt], bl[nt]);   // hi*lo
                mma_bf16(acc[mt][nt], al[mt], bh[nt]);   // lo*hi
                mma_bf16(acc[mt][nt], ah[mt], bh[nt]);   // hi*hi
            }
        __syncthreads();
    }

    // epilogue
#pragma unroll
    for (int mt = 0; mt < 2; mt++) {
        const int row = r0 + wm * 32 + mt * 16 + lr;
#pragma unroll
        for (int nt = 0; nt < 4; nt++) {
            const int col = c0 + wn * 32 + nt * 8 + lc * 2;
            const float b0v = bias[col], b1v = bias[col + 1];
            float2 s0, s1;
            s0.x = acc[mt][nt][0] + b0v; s0.y = acc[mt][nt][1] + b1v;
            s1.x = acc[mt][nt][2] + b0v; s1.y = acc[mt][nt][3] + b1v;
            *reinterpret_cast<float2*>(&C[(size_t)row * N + col])       = s0;
            *reinterpret_cast<float2*>(&C[(size_t)(row + 8) * N + col]) = s1;
        }
    }
}

// Wrappers referencing __device__ globals directly (no symbol lookups on host)
__global__ __launch_bounds__(256)
void qkv_gemm_kernel(const float* __restrict__ x,
                     const float* __restrict__ qkv_w,
                     const float* __restrict__ qkv_b)
{
    gemm_bf16x3_body(x, qkv_w, qkv_b, g_qkv, M_ROWS, QKV_N, DIM);
}

__global__ __launch_bounds__(256)
void proj_gemm_kernel(const float* __restrict__ proj_w,
                      const float* __restrict__ proj_b,
                      float* __restrict__ out)
{
    gemm_bf16x3_body(g_ctx, proj_w, proj_b, out, M_ROWS, DIM, DIM);
}

// ---------------------------------------------------------------------------
// Fused attention (proven in R6/R7): one block per (window b, head h).
// ---------------------------------------------------------------------------
#define QPAD 52

__global__ __launch_bounds__(256)
void attn_kernel(float* __restrict__ attn_out, int write_attn)
{
    const int bh = blockIdx.x;
    const int b  = bh / NHEAD;
    const int h  = bh % NHEAD;
    const int tid = threadIdx.x;
    const int mb = b % NWIN;

    __shared__ float4 qs[QPAD * 9];
    __shared__ float4 ksT4[8 * QPAD];
    __shared__ float4 vs[NTOK * 8];
    __shared__ float  s[NTOK * 56];

    const size_t row0 = (size_t)b * NTOK;
    const int qoff = h * HDIM;
    const float scale = 0.1767766952966369f;

    for (int e = tid; e < QPAD * 8; e += 256) {
        const int i = e >> 3, c = e & 7;
        if (i < NTOK) {
            const size_t base = (row0 + i) * QKV_N + qoff + c * 4;
            float4 qv = *reinterpret_cast<const float4*>(&g_qkv[base]);
            qv.x *= scale; qv.y *= scale; qv.z *= scale; qv.w *= scale;
            qs[i * 9 + c] = qv;
            ksT4[c * QPAD + i] = *reinterpret_cast<const float4*>(&g_qkv[base + DIM]);
            vs[i * 8 + c] = *reinterpret_cast<const float4*>(&g_qkv[base + 2 * DIM]);
        } else {
            const float4 z = make_float4(0.f, 0.f, 0.f, 0.f);
            qs[i * 9 + c] = z;
            ksT4[c * QPAD + i] = z;
        }
    }
    __syncthreads();

    const float* bm = &g_bm[(size_t)(mb * NHEAD + h) * NN];
    if (tid < 169) {
        const int ti = tid / 13, tj = tid % 13;
        const int i0 = ti * 4, j0 = tj * 4;
        float acc[4][4];
#pragma unroll
        for (int u = 0; u < 4; u++)
#pragma unroll
            for (int v = 0; v < 4; v++) acc[u][v] = 0.f;
#pragma unroll
        for (int c = 0; c < 8; c++) {
            float4 qv[4], kv[4];
#pragma unroll
            for (int u = 0; u < 4; u++) qv[u] = qs[(i0 + u) * 9 + c];
#pragma unroll
            for (int v = 0; v < 4; v++) kv[v] = ksT4[c * QPAD + j0 + v];
#pragma unroll
            for (int u = 0; u < 4; u++)
#pragma unroll
                for (int v = 0; v < 4; v++)
                    acc[u][v] += qv[u].x * kv[v].x + qv[u].y * kv[v].y
                               + qv[u].z * kv[v].z + qv[u].w * kv[v].w;
        }
#pragma unroll
        for (int u = 0; u < 4; u++) {
            const int i = i0 + u;
            if (i < NTOK) {
#pragma unroll
                for (int v = 0; v < 4; v++) {
                    const int j = j0 + v;
                    if (j < NTOK)
                        s[i * 56 + j] = acc[u][v] + bm[i * NTOK + j];
                }
            }
        }
    }
    __syncthreads();

    {
        const int row = tid >> 2;
        const int q4  = tid & 3;
        const bool act = (row < NTOK);
        float* rowp = &s[(act ? row : 0) * 56];
        float mx = -1e30f;
        if (act) for (int j = q4; j < NTOK; j += 4) mx = fmaxf(mx, rowp[j]);
        mx = fmaxf(mx, __shfl_xor_sync(0xffffffffu, mx, 1));
        mx = fmaxf(mx, __shfl_xor_sync(0xffffffffu, mx, 2));
        float sum = 0.f;
        if (act) {
            for (int j = q4; j < NTOK; j += 4) {
                const float ev = __expf(rowp[j] - mx);
                rowp[j] = ev;
                sum += ev;
            }
        }
        sum += __shfl_xor_sync(0xffffffffu, sum, 1);
        sum += __shfl_xor_sync(0xffffffffu, sum, 2);
        if (act) {
            const float inv = 1.f / sum;
            for (int j = q4; j < NTOK; j += 4) rowp[j] *= inv;
        }
    }
    __syncthreads();

    if (write_attn) {
        float* ao = &attn_out[(size_t)bh * NN];
        for (int e = tid; e < NN; e += 256) {
            const int i = e / NTOK, j = e - i * NTOK;
            ao[e] = s[i * 56 + j];
        }
    }

    if (tid < 200) {
        const int ip = tid >> 3, d4 = tid & 7;
        const int i0 = ip * 2;
        float4 a0 = make_float4(0.f, 0.f, 0.f, 0.f);
        float4 a1 = make_float4(0.f, 0.f, 0.f, 0.f);
        const float* s0 = &s[i0 * 56];
        const bool two = (i0 + 1 < NTOK);
#pragma unroll
        for (int j = 0; j < NTOK; j++) {
            const float4 vv = vs[j * 8 + d4];
            const float p0 = s0[j];
            a0.x += p0 * vv.x; a0.y += p0 * vv.y;
            a0.z += p0 * vv.z; a0.w += p0 * vv.w;
            const float p1 = two ? s0[56 + j] : 0.f;
            a1.x += p1 * vv.x; a1.y += p1 * vv.y;
            a1.z += p1 * vv.z; a1.w += p1 * vv.w;
        }
        *reinterpret_cast<float4*>(&g_ctx[(row0 + i0) * DIM + qoff + d4 * 4]) = a0;
        if (two)
            *reinterpret_cast<float4*>(&g_ctx[(row0 + i0 + 1) * DIM + qoff + d4 * 4]) = a1;
    }
}

extern "C" void kernel_launch(void* const* d_in, const int* in_sizes, int n_in,
                              void* d_out, int out_size)
{
    const float* x      = (const float*)d_in[0];
    const float* mask   = (const float*)d_in[1];
    const float* qkv_w  = (const float*)d_in[2];
    const float* qkv_b  = (const float*)d_in[3];
    const float* proj_w = (const float*)d_in[4];
    const float* proj_b = (const float*)d_in[5];
    const float* rpb    = (const float*)d_in[6];
    const int*   relidx = (const int*)d_in[7];
    float* out = (float*)d_out;

    const long out_elems  = (long)M_ROWS * DIM;                 // 38,535,168
    const long attn_elems = (long)B_TOT * NHEAD * NN;           // 59,006,976
    const int write_attn = ((long)out_size >= out_elems + attn_elems) ? 1 : 0;
    float* attn_out = out + out_elems;

    // 0) bias+mask table
    bm_kernel<<<NWIN * NHEAD, 256>>>(mask, rpb, relidx);

    // 1) QKV GEMM: [200704,192] @ [192,576] (bf16x3 tensor cores)
    qkv_gemm_kernel<<<dim3(QKV_N / 64, M_ROWS / 128), 256>>>(x, qkv_w, qkv_b);

    // 2) fused window attention
    attn_kernel<<<B_TOT * NHEAD, 256>>>(attn_out, write_attn);

    // 3) projection: [200704,192] @ [192,192] (bf16x3 tensor cores)
    proj_gemm_kernel<<<dim3(DIM / 64, M_ROWS / 128), 256>>>(proj_w, proj_b, out);
}